// round 15
// baseline (speedup 1.0000x reference)
#include <cuda_runtime.h>

#define T_STEPS 730
#define N_GRID  8000
#define NZ      1e-5f

__constant__ float c_LO[18] = {-3.f, 0.f, 0.f, 0.f, 0.f, 0.f, 0.f, 0.f, 0.005f, 1.f, 0.f, 1.f, 0.f, 1.f, 0.f, 0.f, 0.f, 0.f};
__constant__ float c_HI[18] = { 5.f,20.f, 1.f, 1.f, 5.f,50.f, 1.f, 1.f, 0.995f, 2000.f, 20.f, 300.f, 1.f, 5.f, 1.f, 1.f, 1.f, 1.f};

__device__ __forceinline__ float fast_ex2(float a) {
    float r;
    asm("ex2.approx.f32 %0, %1;" : "=f"(r) : "f"(a));
    return r;
}

__global__ __launch_bounds__(64) void prms_kernel(
    const float* __restrict__ x,      // [T_STEPS, N_GRID, 3]
    const float* __restrict__ params, // [T_STEPS, N_GRID, 18]
    float* __restrict__ out)          // [T_STEPS, N_GRID]
{
    const int g = blockIdx.x * blockDim.x + threadIdx.x;
    if (g >= N_GRID) return;

    // ---- per-cell parameters from the LAST timestep slice ----
    const float* pp = params + ((size_t)(T_STEPS - 1) * N_GRID + g) * 18;
    float pr[18];
#pragma unroll
    for (int i = 0; i < 18; i++) {
        float s = 1.0f / (1.0f + expf(-pp[i]));
        pr[i] = c_LO[i] + s * (c_HI[i] - c_LO[i]);
    }
    const float tt     = pr[0],  ddf   = pr[1],  alpha = pr[2],  beta  = pr[3];
    const float stor   = pr[4],  retip = pr[5],  fscn  = pr[6],  scx   = pr[7];
    const float flz    = pr[8],  stot  = pr[9],  cgw   = pr[10], resmax= pr[11];
    const float k1     = pr[12], k2    = pr[13], k3    = pr[14], k4    = pr[15];
    const float k5     = pr[16], k6    = pr[17];

    const float scn        = fscn * scx;
    const float remx       = (1.0f - flz) * stot;
    const float smax       = flz * stot;
    const float inv_remx   = 1.0f / remx;
    const float inv_smax   = 1.0f / smax;
    const float inv_resmax = 1.0f / resmax;
    const float one_m_beta = 1.0f - beta;
    const float one_m_alpha= 1.0f - alpha;
    const float c2         = (scx - scn) * inv_remx;   // sro_lin slope (> 0)
    const float lg2k1      = log2f(k1);                // fold k1 into pow exponent

    // ---- state (upper: snow..smav ; lower: res, gw) ----
    float snow = 0.001f, xin = 0.001f, rstor = 0.001f, rechr = 0.001f, smav = 0.001f;
    float res = 0.001f, gw = 0.001f;

    // ---- depth-2 register prefetch pipeline for x ----
    float Pb[2], Tb[2], Eb[2];
    {
        const float* x0 = x + (size_t)g * 3;                      // t = 0
        Pb[0] = x0[0]; Tb[0] = x0[1]; Eb[0] = x0[2];
        const float* x1 = x + ((size_t)N_GRID + g) * 3;           // t = 1
        Pb[1] = x1[0]; Tb[1] = x1[1]; Eb[1] = x1[2];
    }
    const float* xp = x + ((size_t)2 * N_GRID + g) * 3;   // x[t+2] walker
    float*       op = out + g;                            // out[t-1] walker

    // pipeline carries: outputs of upper(t) consumed by lower(t) next iter
    float sas_c, sro_c, excs_c;

    // =================== upper(t) — R10 exact, minus 2 dead clamps ===================
    auto upper = [&](float P, float Tc, float Ep,
                     float& sas_o, float& sro_o, float& excs_o) {
        // ---- snow (clamp lemma) ----
        const float flux_ps  = (Tc <= tt) ? P : 0.0f;
        const float flux_pr  = P - flux_ps;
        const float snow1    = snow + flux_ps;
        const float mpot     = fmaxf(ddf * (Tc - tt), 0.0f);
        const float flux_m   = fminf(mpot, snow1);
        snow = fmaxf(snow1 - mpot, NZ);

        // ---- interception (lemmas) ----
        const float flux_pim = flux_pr * one_m_beta;
        const float flux_psm = flux_pr * beta;
        const float flux_pby = flux_psm * one_m_alpha;
        const float flux_pin = flux_psm * alpha;
        const float xin1 = xin + flux_pin;
        const float flux_ptf = fmaxf(xin1 - stor, 0.0f);
        const float xin2 = fminf(xin1, stor);
        const float epb  = Ep * beta;
        const float flux_ein = fminf(epb, xin2);
        xin = fmaxf(xin2 - epb, NZ);

        // ---- impervious storage (lemmas) ----
        const float rs1 = rstor + fmaf(flux_m, one_m_beta, flux_pim);
        const float flux_sas = fmaxf(rs1 - retip, 0.0f);
        const float rs2 = fminf(rs1, retip);
        const float eib = one_m_beta * Ep;
        const float flux_eim = fminf(eib, rs2);
        rstor = fmaxf(rs2 - eib, NZ);

        // ---- surface runoff / recharge ----
        // fmaf(c2,rechr,scn) > 0 always (c2>0, rechr>=NZ, scn>0): fmax(.,0) dead
        const float sro_lin = fminf(fmaf(c2, rechr, scn), 1.0f);
        const float inflow  = fmaf(flux_m, beta, flux_ptf) + flux_pby;
        const float flux_sro = sro_lin * inflow;
        const float flux_inf = inflow - flux_sro;
        const float re1 = rechr + flux_inf;
        const float flux_pc = fmaxf(re1 - remx, 0.0f);
        const float re2 = fminf(re1, remx);
        const float ep_net = Ep - flux_ein - flux_eim;
        const float evap_max_a = re2 * inv_remx * ep_net;      // R10 exact form
        const float flux_ea = fminf(evap_max_a, re2);
        rechr = fmaxf(re2 - flux_ea, NZ);

        // ---- soil moisture ----
        const float sm1 = smav + flux_pc;
        const float flux_excs = fmaxf(sm1 - smax, 0.0f);
        const float sm2 = fminf(sm1, smax);
        // ep_net - flux_ea >= 0 and sm2 > 0: fmax(.,0) dead
        float transp = (rechr < ep_net)
                         ? fminf(sm2 * inv_smax * (ep_net - flux_ea), sm2)
                         : 0.0f;
        smav = fmaxf(sm2 - transp, NZ);

        sas_o = flux_sas; sro_o = flux_sro; excs_o = flux_excs;
    };

    // =================== lower(t) — R10 exact ===================
    auto lower = [&](float flux_sas, float flux_sro, float flux_excs) -> float {
        const float flux_sep  = fminf(cgw, flux_excs);
        const float flux_qres = flux_excs - flux_sep;          // >= 0 exactly
        res += flux_qres;
        const float ratio = res * inv_resmax;
        float flux_gad = fast_ex2(fmaf(k2, __log2f(ratio), lg2k1));  // k1*ratio^k2
        flux_gad = fminf(flux_gad, res);
        res = fmaxf(res - flux_gad, NZ);
        float flux_ras = fminf(fmaf(k4 * res, res, k3 * res), res);
        res = fmaxf(res - flux_ras, NZ);

        gw += flux_gad + flux_sep;
        const float flux_bas = k5 * gw;
        gw = fmaxf(gw - flux_bas, NZ);
        const float flux_snk = k6 * gw;
        gw = fmaxf(gw - flux_snk, NZ);

        return flux_sas + flux_sro + flux_bas + flux_ras;
    };

    // ---- prologue: FULL t=0 iteration (read slot 0, prefetch x[2] -> slot 0) ----
    {
        const float P = Pb[0], Tc = Tb[0], Ep = Eb[0];
        Pb[0] = xp[0]; Tb[0] = xp[1]; Eb[0] = xp[2];      // x[2] -> slot 0
        xp += (size_t)N_GRID * 3;                          // xp now at x[3]
        upper(P, Tc, Ep, sas_c, sro_c, excs_c);
    }

    // ---- pipelined main loop: lower(t-1) || upper(t), t = 1..T-1 ----
#pragma unroll 2
    for (int t = 1; t < T_STEPS; t++) {
        const int b = t & 1;
        const float P  = Pb[b];
        const float Tc = Tb[b];
        const float Ep = Eb[b];
        if (t + 2 < T_STEPS) {                // prefetch x[t+2] into slot b
            Pb[b] = xp[0]; Tb[b] = xp[1]; Eb[b] = xp[2];
        }
        xp += (size_t)N_GRID * 3;             // advance EVERY iteration

        // lower chain for step t-1 (independent of upper(t))
        const float q_prev = lower(sas_c, sro_c, excs_c);

        // upper chain for step t
        float sas_n, sro_n, excs_n;
        upper(P, Tc, Ep, sas_n, sro_n, excs_n);

        *op = q_prev;                          // out[t-1]
        op += N_GRID;

        sas_c = sas_n; sro_c = sro_n; excs_c = excs_n;
    }

    // ---- epilogue: lower(T-1) ----
    *op = lower(sas_c, sro_c, excs_c);
}

extern "C" void kernel_launch(void* const* d_in, const int* in_sizes, int n_in,
                              void* d_out, int out_size) {
    // Identify inputs by element count (robust to ordering):
    //   x:          730*8000*3  = 17,520,000
    //   parameters: 730*8000*18 = 105,120,000
    const float* x = nullptr;
    const float* params = nullptr;
    for (int i = 0; i < n_in; i++) {
        if (in_sizes[i] == T_STEPS * N_GRID * 3)  x = (const float*)d_in[i];
        if (in_sizes[i] == T_STEPS * N_GRID * 18) params = (const float*)d_in[i];
    }
    float* out = (float*)d_out;

    const int threads = 64;
    const int blocks = (N_GRID + threads - 1) / threads;  // 125 blocks
    prms_kernel<<<blocks, threads>>>(x, params, out);
}

// round 16
// speedup vs baseline: 1.2142x; 1.2142x over previous
#include <cuda_runtime.h>

#define T_STEPS 730
#define N_GRID  8000
#define NZ      1e-5f

__constant__ float c_LO[18] = {-3.f, 0.f, 0.f, 0.f, 0.f, 0.f, 0.f, 0.f, 0.005f, 1.f, 0.f, 1.f, 0.f, 1.f, 0.f, 0.f, 0.f, 0.f};
__constant__ float c_HI[18] = { 5.f,20.f, 1.f, 1.f, 5.f,50.f, 1.f, 1.f, 0.995f, 2000.f, 20.f, 300.f, 1.f, 5.f, 1.f, 1.f, 1.f, 1.f};

__device__ __forceinline__ float fast_ex2(float a) {
    float r;
    asm("ex2.approx.f32 %0, %1;" : "=f"(r) : "f"(a));
    return r;
}

__global__ __launch_bounds__(64) void prms_kernel(
    const float* __restrict__ x,      // [T_STEPS, N_GRID, 3]
    const float* __restrict__ params, // [T_STEPS, N_GRID, 18]
    float* __restrict__ out)          // [T_STEPS, N_GRID]
{
    const int g = blockIdx.x * blockDim.x + threadIdx.x;
    if (g >= N_GRID) return;

    // ---- per-cell parameters from the LAST timestep slice ----
    const float* pp = params + ((size_t)(T_STEPS - 1) * N_GRID + g) * 18;
    float pr[18];
#pragma unroll
    for (int i = 0; i < 18; i++) {
        float s = 1.0f / (1.0f + expf(-pp[i]));
        pr[i] = c_LO[i] + s * (c_HI[i] - c_LO[i]);
    }
    const float tt     = pr[0],  ddf   = pr[1],  alpha = pr[2],  beta  = pr[3];
    const float stor   = pr[4],  retip = pr[5],  fscn  = pr[6],  scx   = pr[7];
    const float flz    = pr[8],  stot  = pr[9],  cgw   = pr[10], resmax= pr[11];
    const float k1     = pr[12], k2    = pr[13], k3    = pr[14], k4    = pr[15];
    const float k5     = pr[16], k6    = pr[17];

    const float scn        = fscn * scx;
    const float remx       = (1.0f - flz) * stot;
    const float smax       = flz * stot;
    const float inv_remx   = 1.0f / remx;
    const float inv_smax   = 1.0f / smax;
    const float inv_resmax = 1.0f / resmax;
    const float one_m_beta = 1.0f - beta;
    const float one_m_alpha= 1.0f - alpha;
    const float c2         = (scx - scn) * inv_remx;   // sro_lin slope (> 0)
    const float lg2k1      = log2f(k1);                // fold k1 into pow exponent

    // ---- state (upper: snow..smav ; lower: res, gw) ----
    float snow = 0.001f, xin = 0.001f, rstor = 0.001f, rechr = 0.001f, smav = 0.001f;
    float res = 0.001f, gw = 0.001f;

    // ---- depth-2 register prefetch pipeline for x ----
    float Pb[2], Tb[2], Eb[2];
    {
        const float* x0 = x + (size_t)g * 3;                      // t = 0
        Pb[0] = x0[0]; Tb[0] = x0[1]; Eb[0] = x0[2];
        const float* x1 = x + ((size_t)N_GRID + g) * 3;           // t = 1
        Pb[1] = x1[0]; Tb[1] = x1[1]; Eb[1] = x1[2];
    }
    const float* xp = x + ((size_t)2 * N_GRID + g) * 3;   // x[t+2] walker
    float*       op = out + g;                            // out[t-1] walker

    // pipeline carries: outputs of upper(t) consumed by lower(t) next iter
    float sas_c, sro_c, excs_c;

    // ============ upper(t) — R10 exact except ONE dead-clamp removal ============
    auto upper = [&](float P, float Tc, float Ep,
                     float& sas_o, float& sro_o, float& excs_o) {
        // ---- snow (clamp lemma) ----
        const float flux_ps  = (Tc <= tt) ? P : 0.0f;
        const float flux_pr  = P - flux_ps;
        const float snow1    = snow + flux_ps;
        const float mpot     = fmaxf(ddf * (Tc - tt), 0.0f);
        const float flux_m   = fminf(mpot, snow1);
        snow = fmaxf(snow1 - mpot, NZ);

        // ---- interception (lemmas) ----
        const float flux_pim = flux_pr * one_m_beta;
        const float flux_psm = flux_pr * beta;
        const float flux_pby = flux_psm * one_m_alpha;
        const float flux_pin = flux_psm * alpha;
        const float xin1 = xin + flux_pin;
        const float flux_ptf = fmaxf(xin1 - stor, 0.0f);
        const float xin2 = fminf(xin1, stor);
        const float epb  = Ep * beta;
        const float flux_ein = fminf(epb, xin2);
        xin = fmaxf(xin2 - epb, NZ);

        // ---- impervious storage (lemmas) ----
        const float rs1 = rstor + fmaf(flux_m, one_m_beta, flux_pim);
        const float flux_sas = fmaxf(rs1 - retip, 0.0f);
        const float rs2 = fminf(rs1, retip);
        const float eib = one_m_beta * Ep;
        const float flux_eim = fminf(eib, rs2);
        rstor = fmaxf(rs2 - eib, NZ);

        // ---- surface runoff / recharge ----
        // ONLY change vs R10: fmaf(c2,rechr,scn) > 0 always, so fmax(.,0) is dead.
        // This op sits on the rechr recurrence cycle.
        const float sro_lin = fminf(fmaf(c2, rechr, scn), 1.0f);
        const float inflow  = fmaf(flux_m, beta, flux_ptf) + flux_pby;
        const float flux_sro = sro_lin * inflow;
        const float flux_inf = inflow - flux_sro;
        const float re1 = rechr + flux_inf;
        const float flux_pc = fmaxf(re1 - remx, 0.0f);
        const float re2 = fminf(re1, remx);
        const float ep_net = Ep - flux_ein - flux_eim;
        const float evap_max_a = re2 * inv_remx * ep_net;
        const float flux_ea = fminf(evap_max_a, re2);
        rechr = fmaxf(re2 - flux_ea, NZ);

        // ---- soil moisture (R10 exact, clamp restored) ----
        const float sm1 = smav + flux_pc;
        const float flux_excs = fmaxf(sm1 - smax, 0.0f);
        const float sm2 = fminf(sm1, smax);
        float transp = (rechr < ep_net)
                         ? fminf(fmaxf(sm2 * inv_smax * (ep_net - flux_ea), 0.0f), sm2)
                         : 0.0f;
        smav = fmaxf(sm2 - transp, NZ);

        sas_o = flux_sas; sro_o = flux_sro; excs_o = flux_excs;
    };

    // =================== lower(t) — R10 exact ===================
    auto lower = [&](float flux_sas, float flux_sro, float flux_excs) -> float {
        const float flux_sep  = fminf(cgw, flux_excs);
        const float flux_qres = flux_excs - flux_sep;          // >= 0 exactly
        res += flux_qres;
        const float ratio = res * inv_resmax;
        float flux_gad = fast_ex2(fmaf(k2, __log2f(ratio), lg2k1));  // k1*ratio^k2
        flux_gad = fminf(flux_gad, res);
        res = fmaxf(res - flux_gad, NZ);
        float flux_ras = fminf(fmaf(k4 * res, res, k3 * res), res);
        res = fmaxf(res - flux_ras, NZ);

        gw += flux_gad + flux_sep;
        const float flux_bas = k5 * gw;
        gw = fmaxf(gw - flux_bas, NZ);
        const float flux_snk = k6 * gw;
        gw = fmaxf(gw - flux_snk, NZ);

        return flux_sas + flux_sro + flux_bas + flux_ras;
    };

    // ---- prologue: FULL t=0 iteration (read slot 0, prefetch x[2] -> slot 0) ----
    {
        const float P = Pb[0], Tc = Tb[0], Ep = Eb[0];
        Pb[0] = xp[0]; Tb[0] = xp[1]; Eb[0] = xp[2];      // x[2] -> slot 0
        xp += (size_t)N_GRID * 3;                          // xp now at x[3]
        upper(P, Tc, Ep, sas_c, sro_c, excs_c);
    }

    // ---- pipelined main loop: lower(t-1) || upper(t), t = 1..T-1 ----
#pragma unroll 2
    for (int t = 1; t < T_STEPS; t++) {
        const int b = t & 1;
        const float P  = Pb[b];
        const float Tc = Tb[b];
        const float Ep = Eb[b];
        if (t + 2 < T_STEPS) {                // prefetch x[t+2] into slot b
            Pb[b] = xp[0]; Tb[b] = xp[1]; Eb[b] = xp[2];
        }
        xp += (size_t)N_GRID * 3;             // advance EVERY iteration

        // lower chain for step t-1 (independent of upper(t))
        const float q_prev = lower(sas_c, sro_c, excs_c);

        // upper chain for step t
        float sas_n, sro_n, excs_n;
        upper(P, Tc, Ep, sas_n, sro_n, excs_n);

        *op = q_prev;                          // out[t-1]
        op += N_GRID;

        sas_c = sas_n; sro_c = sro_n; excs_c = excs_n;
    }

    // ---- epilogue: lower(T-1) ----
    *op = lower(sas_c, sro_c, excs_c);
}

extern "C" void kernel_launch(void* const* d_in, const int* in_sizes, int n_in,
                              void* d_out, int out_size) {
    // Identify inputs by element count (robust to ordering):
    //   x:          730*8000*3  = 17,520,000
    //   parameters: 730*8000*18 = 105,120,000
    const float* x = nullptr;
    const float* params = nullptr;
    for (int i = 0; i < n_in; i++) {
        if (in_sizes[i] == T_STEPS * N_GRID * 3)  x = (const float*)d_in[i];
        if (in_sizes[i] == T_STEPS * N_GRID * 18) params = (const float*)d_in[i];
    }
    float* out = (float*)d_out;

    const int threads = 64;
    const int blocks = (N_GRID + threads - 1) / threads;  // 125 blocks
    prms_kernel<<<blocks, threads>>>(x, params, out);
}